// round 3
// baseline (speedup 1.0000x reference)
#include <cuda_runtime.h>

#define NMAX 50000
#define EMAX 800000
#define D 128
#define H 8
#define ATT_SCALE 0.25f   // 1/sqrt(16)

// ---------------- scratch (device globals; no runtime allocation) ----------
__device__ __align__(16) float g_q[NMAX * D];
__device__ __align__(16) float g_k[NMAX * D];
__device__ __align__(16) float g_v[NMAX * D];
__device__ __align__(16) float g_s[NMAX * D];
__device__ __align__(16) float g_h[NMAX * D];     // inter-layer hidden
__device__ __align__(16) float g_msg[NMAX * D];   // unnormalized message accumulator
__device__ __align__(16) float g_alpha[(size_t)EMAX * H];
__device__ float g_m[NMAX * H];     // segment max
__device__ float g_den[NMAX * H];   // segment sum of exp
__device__ int   g_src[EMAX];
__device__ int   g_dst[EMAX];
__device__ int   g_is64;

// ---------------- edge_index dtype detection + conversion ------------------
// If edge_index is int64 (values < 2^31), every odd int32 word is zero.
// 256 samples -> P(misclassify int32 data) = (1/50000)^256 ~ 0.
__global__ void detect_kernel(const int* __restrict__ ei32)
{
    __shared__ int any_nonzero;
    if (threadIdx.x == 0) any_nonzero = 0;
    __syncthreads();
    int v = ei32[2 * threadIdx.x + 1];   // max index 511 < 1.6M, safe either way
    if (v != 0) any_nonzero = 1;         // benign race: all writers store 1
    __syncthreads();
    if (threadIdx.x == 0) g_is64 = any_nonzero ? 0 : 1;
}

__global__ void convert_kernel(const int* __restrict__ ei32, int E)
{
    int e = blockIdx.x * blockDim.x + threadIdx.x;
    if (e >= E) return;
    if (g_is64) {
        g_src[e] = ei32[2 * (size_t)e];
        g_dst[e] = ei32[2 * ((size_t)E + e)];
    } else {
        g_src[e] = ei32[e];
        g_dst[e] = ei32[(size_t)E + e];
    }
}

// ---------------- GEMM: Y = X @ W + b,  X:[N,128] W:[128,128] --------------
#define BM 64
#define BN 64
#define BK 32

__global__ void gemm_bias_kernel(const float* __restrict__ Xin,
                                 const float* __restrict__ W,
                                 const float* __restrict__ bias,
                                 int which,   // 0:q 1:k 2:v 3:s
                                 int N)
{
    const float* X = Xin ? Xin : g_h;
    float* Y = (which == 0) ? g_q : (which == 1) ? g_k : (which == 2) ? g_v : g_s;

    __shared__ float Xs[BM][BK + 1];
    __shared__ float Ws[BK][BN + 1];

    int bx = blockIdx.x;             // 0..1 (column tiles)
    int by = blockIdx.y;             // row tiles
    int tid = threadIdx.x;           // 256 threads
    int tx = tid & 15;
    int ty = tid >> 4;
    int row0 = by * BM;
    int col0 = bx * BN;

    float acc[4][4];
#pragma unroll
    for (int i = 0; i < 4; i++)
#pragma unroll
        for (int j = 0; j < 4; j++) acc[i][j] = 0.f;

    for (int kk = 0; kk < 128; kk += BK) {
        // load X tile: 64x32
#pragma unroll
        for (int i = 0; i < 8; i++) {
            int idx = tid + i * 256;
            int r = idx >> 5, c = idx & 31;
            int gr = row0 + r;
            Xs[r][c] = (gr < N) ? X[(size_t)gr * 128 + kk + c] : 0.f;
        }
        // load W tile: 32x64
#pragma unroll
        for (int i = 0; i < 8; i++) {
            int idx = tid + i * 256;
            int r = idx >> 6, c = idx & 63;
            Ws[r][c] = W[(size_t)(kk + r) * 128 + col0 + c];
        }
        __syncthreads();

#pragma unroll
        for (int k = 0; k < BK; k++) {
            float a[4], b[4];
#pragma unroll
            for (int i = 0; i < 4; i++) a[i] = Xs[ty * 4 + i][k];
#pragma unroll
            for (int j = 0; j < 4; j++) b[j] = Ws[k][tx * 4 + j];
#pragma unroll
            for (int i = 0; i < 4; i++)
#pragma unroll
                for (int j = 0; j < 4; j++) acc[i][j] += a[i] * b[j];
        }
        __syncthreads();
    }

#pragma unroll
    for (int i = 0; i < 4; i++) {
        int r = row0 + ty * 4 + i;
        if (r < N) {
#pragma unroll
            for (int j = 0; j < 4; j++) {
                int c = col0 + tx * 4 + j;
                Y[(size_t)r * 128 + c] = acc[i][j] + bias[c];
            }
        }
    }
}

// ---------------- init m/den/msg -------------------------------------------
__global__ void init_kernel(int N)
{
    int i = blockIdx.x * blockDim.x + threadIdx.x;
    if (i < N * H) {
        g_m[i] = __int_as_float(0xff800000);  // -inf
        g_den[i] = 0.f;
    }
    if (i < N * D) g_msg[i] = 0.f;
}

// ---------------- pass B: alpha + segment max -------------------------------
__device__ __forceinline__ void atomicMaxFloat(float* addr, float val)
{
    if (val >= 0.f) atomicMax((int*)addr, __float_as_int(val));
    else            atomicMin((unsigned int*)addr, __float_as_uint(val));
}

__global__ void edge_alpha_kernel(int E)
{
    int e = (int)((blockIdx.x * (unsigned)blockDim.x + threadIdx.x) >> 5);
    int lane = threadIdx.x & 31;
    if (e >= E) return;
    int s = g_src[e];
    int d = g_dst[e];

    float4 qv = __ldg((const float4*)(g_q + (size_t)d * D) + lane);
    float4 kv = __ldg((const float4*)(g_k + (size_t)s * D) + lane);
    float p = qv.x * kv.x + qv.y * kv.y + qv.z * kv.z + qv.w * kv.w;
    p += __shfl_xor_sync(0xffffffffu, p, 1);
    p += __shfl_xor_sync(0xffffffffu, p, 2);

    if ((lane & 3) == 0) {
        int h = lane >> 2;
        float a = p * ATT_SCALE;
        g_alpha[(size_t)e * H + h] = a;
        atomicMaxFloat(&g_m[(size_t)d * H + h], a);
    }
}

// ---------------- pass C: exp, denom, scatter message -----------------------
__global__ void edge_message_kernel(int E)
{
    int e = (int)((blockIdx.x * (unsigned)blockDim.x + threadIdx.x) >> 5);
    int lane = threadIdx.x & 31;
    if (e >= E) return;
    int s = g_src[e];
    int d = g_dst[e];
    int h = lane >> 2;

    float a = __expf(g_alpha[(size_t)e * H + h] - __ldg(&g_m[(size_t)d * H + h]));
    if ((lane & 3) == 0) atomicAdd(&g_den[(size_t)d * H + h], a);

    float4 vv = __ldg((const float4*)(g_v + (size_t)s * D) + lane);
    float* mp = g_msg + (size_t)d * D + lane * 4;
    atomicAdd(mp + 0, a * vv.x);
    atomicAdd(mp + 1, a * vv.y);
    atomicAdd(mp + 2, a * vv.z);
    atomicAdd(mp + 3, a * vv.w);
}

// ---------------- finalize: out = skip + msg/denom (+relu) ------------------
__global__ void finalize_kernel(float* __restrict__ outp, int N, int do_relu)
{
    int idx = blockIdx.x * blockDim.x + threadIdx.x;
    if (idx >= N * D) return;
    int n = idx >> 7;          // /128
    int c = idx & 127;
    int h = c >> 4;
    float den = g_den[n * H + h];
    float mterm = (den > 0.f) ? g_msg[idx] / den : 0.f;
    float o = g_s[idx] + mterm;
    if (do_relu) o = fmaxf(o, 0.f);
    float* op = outp ? outp : g_h;
    op[idx] = o;
}

// ---------------- host ------------------------------------------------------
extern "C" void kernel_launch(void* const* d_in, const int* in_sizes, int n_in,
                              void* d_out, int out_size)
{
    const float* x = (const float*)d_in[0];
    const int* ei32 = (const int*)d_in[1];   // int32 view; dtype detected on device
    int N = in_sizes[0] / 128;
    int E = in_sizes[1] / 2;

    const float* W[2][4] = {
        {(const float*)d_in[3], (const float*)d_in[5], (const float*)d_in[7], (const float*)d_in[9]},
        {(const float*)d_in[11], (const float*)d_in[13], (const float*)d_in[15], (const float*)d_in[17]}
    };
    const float* B[2][4] = {
        {(const float*)d_in[4], (const float*)d_in[6], (const float*)d_in[8], (const float*)d_in[10]},
        {(const float*)d_in[12], (const float*)d_in[14], (const float*)d_in[16], (const float*)d_in[18]}
    };

    detect_kernel<<<1, 256>>>(ei32);
    convert_kernel<<<(E + 255) / 256, 256>>>(ei32, E);

    dim3 ggrid(128 / BN, (N + BM - 1) / BM);
    int nd_blocks = (N * D + 255) / 256;
    int edge_blocks = (E + 7) / 8;   // 8 edges (warps) per 256-thread block

    for (int layer = 0; layer < 2; layer++) {
        const float* xin = (layer == 0) ? x : nullptr;   // nullptr -> g_h
        for (int w = 0; w < 4; w++)
            gemm_bias_kernel<<<ggrid, 256>>>(xin, W[layer][w], B[layer][w], w, N);
        init_kernel<<<nd_blocks, 256>>>(N);
        edge_alpha_kernel<<<edge_blocks, 256>>>(E);
        edge_message_kernel<<<edge_blocks, 256>>>(E);
        finalize_kernel<<<nd_blocks, 256>>>(layer == 0 ? nullptr : (float*)d_out, N,
                                            layer == 0 ? 1 : 0);
    }
}